// round 8
// baseline (speedup 1.0000x reference)
#include <cuda_runtime.h>
#include <cuda_bf16.h>
#include <cstdint>

#define B_  32
#define S_  512
#define H_  1024
#define V_  250002

#define TOK (B_ * S_)          // 16384
#define OFF_DENSE  0
#define OFF_SPARSE (B_ * H_)                 // 32768
#define OFF_MV     (OFF_SPARSE + B_ * V_)    // 8032832

#define EPS 1e-12f

// ---------------------------------------------------------------------------
// Device-global scratch (allocation-free rule)
// ---------------------------------------------------------------------------
__device__ float g_pooled[B_ * H_];
__device__ float g_masksum[B_];
__device__ float g_tokdot[TOK];
__device__ float g_rowss[TOK];          // per-token sum of squares (mv rows)
__device__ int   g_rowcnt[TOK / 128];   // N-CTA completion counters
__device__ __align__(16) __nv_bfloat16 g_Ahi[TOK * H_];
__device__ __align__(16) __nv_bfloat16 g_Alo[TOK * H_];
__device__ __align__(16) __nv_bfloat16 g_Whi[H_ * H_];
__device__ __align__(16) __nv_bfloat16 g_Wlo[H_ * H_];

// ---------------------------------------------------------------------------
// PTX helpers
// ---------------------------------------------------------------------------
__device__ __forceinline__ uint32_t smem_u32(const void* p) {
    uint32_t a;
    asm("{ .reg .u64 t; cvta.to.shared.u64 t, %1; cvt.u32.u64 %0, t; }"
        : "=r"(a) : "l"(p));
    return a;
}
#define CP16(dst, src) \
    asm volatile("cp.async.cg.shared.global [%0], [%1], 16;" \
                 :: "r"(dst), "l"(src) : "memory")
#define CP_COMMIT() asm volatile("cp.async.commit_group;" ::: "memory")
#define CP_WAIT2()  asm volatile("cp.async.wait_group 2;" ::: "memory")
#define CP_WAIT1()  asm volatile("cp.async.wait_group 1;" ::: "memory")
#define CP_WAIT0()  asm volatile("cp.async.wait_group 0;" ::: "memory")
#define LDSM_X4(r0, r1, r2, r3, addr) \
    asm volatile("ldmatrix.sync.aligned.m8n8.x4.shared.b16 {%0,%1,%2,%3}, [%4];" \
                 : "=r"(r0), "=r"(r1), "=r"(r2), "=r"(r3) : "r"(addr))
#define MMA16816(d, a, b) \
    asm volatile("mma.sync.aligned.m16n8k16.row.col.f32.bf16.bf16.f32 " \
                 "{%0,%1,%2,%3}, {%4,%5,%6,%7}, {%8,%9}, {%0,%1,%2,%3};" \
                 : "+f"((d)[0]), "+f"((d)[1]), "+f"((d)[2]), "+f"((d)[3]) \
                 : "r"((a)[0]), "r"((a)[1]), "r"((a)[2]), "r"((a)[3]), \
                   "r"((b)[0]), "r"((b)[1]))

// ---------------------------------------------------------------------------
// Zero sparse output region + all per-call accumulators/counters
// ---------------------------------------------------------------------------
__global__ void zero_kernel(float* __restrict__ sparse) {
    const int gsz = gridDim.x * blockDim.x;
    const int gtid = blockIdx.x * blockDim.x + threadIdx.x;
    float4 z = make_float4(0.f, 0.f, 0.f, 0.f);

    float4* p = reinterpret_cast<float4*>(sparse);
    for (int i = gtid; i < (B_ * V_) / 4; i += gsz) p[i] = z;

    float4* pp = reinterpret_cast<float4*>(g_pooled);
    for (int i = gtid; i < B_ * H_ / 4; i += gsz) pp[i] = z;

    float4* rs = reinterpret_cast<float4*>(g_rowss);
    for (int i = gtid; i < TOK / 4; i += gsz) rs[i] = z;

    if (gtid < TOK / 128) g_rowcnt[gtid] = 0;
    if (gtid < B_) g_masksum[gtid] = 0.f;
}

// ---------------------------------------------------------------------------
// MEGA PASS: one read of hidden does (a) bf16 hi/lo split, (b) masked-pool
// partial accumulation (atomics), (c) per-token sparse dot, (d) masksum.
// grid: (B_, S_/32). block: 256 (thread t owns h = 4t..4t+3).
// ---------------------------------------------------------------------------
#define SCH 32
__global__ __launch_bounds__(256, 4)
void mega_pass(const float* __restrict__ x,
               const float* __restrict__ mask,
               const float* __restrict__ sw) {
    const int b = blockIdx.x;
    const int s0 = blockIdx.y * SCH;
    const int tid = threadIdx.x;
    const int wid = tid >> 5, lane = tid & 31;

    __shared__ float msk[SCH];
    __shared__ float red[SCH][8];
    if (tid < SCH) msk[tid] = mask[b * S_ + s0 + tid];
    const float4 w4 = *reinterpret_cast<const float4*>(sw + tid * 4);
    __syncthreads();

    // masksum partial (warp 0)
    if (wid == 0) {
        float mv = msk[lane];
#pragma unroll
        for (int o = 16; o > 0; o >>= 1)
            mv += __shfl_down_sync(0xffffffffu, mv, o);
        if (lane == 0) atomicAdd(&g_masksum[b], mv);
    }

    float p0 = 0.f, p1 = 0.f, p2 = 0.f, p3 = 0.f;
    __nv_bfloat162* ahi = reinterpret_cast<__nv_bfloat162*>(g_Ahi);
    __nv_bfloat162* alo = reinterpret_cast<__nv_bfloat162*>(g_Alo);

#pragma unroll 4
    for (int si = 0; si < SCH; si++) {
        const int t = b * S_ + s0 + si;
        const float4 v = *reinterpret_cast<const float4*>(
            x + (size_t)t * H_ + tid * 4);
        __nv_bfloat162 h01 = __floats2bfloat162_rn(v.x, v.y);
        __nv_bfloat162 h23 = __floats2bfloat162_rn(v.z, v.w);
        float2 f01 = __bfloat1622float2(h01);
        float2 f23 = __bfloat1622float2(h23);
        __nv_bfloat162 l01 = __floats2bfloat162_rn(v.x - f01.x, v.y - f01.y);
        __nv_bfloat162 l23 = __floats2bfloat162_rn(v.z - f23.x, v.w - f23.y);
        const size_t o2 = (size_t)t * (H_ / 2) + tid * 2;
        ahi[o2] = h01; ahi[o2 + 1] = h23;
        alo[o2] = l01; alo[o2 + 1] = l23;
        const float mk = msk[si];
        p0 += v.x * mk; p1 += v.y * mk; p2 += v.z * mk; p3 += v.w * mk;
        float d = v.x * w4.x + v.y * w4.y + v.z * w4.z + v.w * w4.w;
#pragma unroll
        for (int o = 16; o > 0; o >>= 1)
            d += __shfl_down_sync(0xffffffffu, d, o);
        if (lane == 0) red[si][wid] = d;
    }
    __syncthreads();
    {
        const int si = tid >> 3, j = tid & 7;
        float d = red[si][j];
        d += __shfl_down_sync(0xffffffffu, d, 4);
        d += __shfl_down_sync(0xffffffffu, d, 2);
        d += __shfl_down_sync(0xffffffffu, d, 1);
        if (j == 0) g_tokdot[b * S_ + s0 + si] = d;
    }
    float* pp = g_pooled + b * H_ + tid * 4;
    atomicAdd(pp + 0, p0);
    atomicAdd(pp + 1, p1);
    atomicAdd(pp + 2, p2);
    atomicAdd(pp + 3, p3);
}

// ---------------------------------------------------------------------------
// Sparse finalize: relu((dot+b)*mask) scatter-add.
// ---------------------------------------------------------------------------
__global__ void sparse_finalize(const float* __restrict__ mask,
                                const float* __restrict__ sb,
                                const int* __restrict__ ids,
                                float* __restrict__ sparse) {
    const int t = blockIdx.x * 256 + threadIdx.x;
    float tw = (g_tokdot[t] + sb[0]) * mask[t];
    if (tw > 0.f) {
        const int b = t / S_;
        const int id = ids[t];
        if (id >= 0 && id < V_)
            atomicAdd(sparse + (size_t)b * V_ + id, tw);
    }
}

// ---------------------------------------------------------------------------
// Split fp32 -> bf16 hi/lo (mv_w)
// ---------------------------------------------------------------------------
__global__ void split_bf16_kernel(const float4* __restrict__ src,
                                  __nv_bfloat162* __restrict__ hi,
                                  __nv_bfloat162* __restrict__ lo, int n4) {
    for (int i = blockIdx.x * blockDim.x + threadIdx.x; i < n4;
         i += gridDim.x * blockDim.x) {
        float4 v = src[i];
        __nv_bfloat162 h01 = __floats2bfloat162_rn(v.x, v.y);
        __nv_bfloat162 h23 = __floats2bfloat162_rn(v.z, v.w);
        float2 f01 = __bfloat1622float2(h01);
        float2 f23 = __bfloat1622float2(h23);
        __nv_bfloat162 l01 = __floats2bfloat162_rn(v.x - f01.x, v.y - f01.y);
        __nv_bfloat162 l23 = __floats2bfloat162_rn(v.z - f23.x, v.w - f23.y);
        hi[i * 2 + 0] = h01;  hi[i * 2 + 1] = h23;
        lo[i * 2 + 0] = l01;  lo[i * 2 + 1] = l23;
    }
}

// ---------------------------------------------------------------------------
// Dense head
// ---------------------------------------------------------------------------
__global__ __launch_bounds__(256, 4)
void dense_kernel2(const float* __restrict__ dw,
                   const float* __restrict__ db,
                   float* __restrict__ out) {
    __shared__ float ws[8][H_ + 1];
    const int tid = threadIdx.x;
    const int h0 = blockIdx.x * 8;
#pragma unroll
    for (int i = 0; i < 32; i++) {
        int idx = tid + i * 256;
        int r = idx >> 10, c = idx & 1023;
        ws[r][c] = dw[(size_t)(h0 + r) * H_ + c];
    }
    __syncthreads();
    const int b = tid >> 3;
    const int hi = tid & 7;
    const float* p = g_pooled + b * H_;
    float acc = 0.f;
#pragma unroll 8
    for (int k = 0; k < H_; k++) acc += p[k] * ws[hi][k];
    const float pinv = 1.f / g_masksum[b];
    out[b * H_ + h0 + hi] = tanhf(acc * pinv + db[h0 + hi]);
}

// ---------------------------------------------------------------------------
// Row L2-normalize in place (dense head rows)
// ---------------------------------------------------------------------------
__global__ void l2norm_kernel(float* __restrict__ data) {
    float4* row = reinterpret_cast<float4*>(data + (size_t)blockIdx.x * H_);
    float4 v = row[threadIdx.x];
    float ss = v.x * v.x + v.y * v.y + v.z * v.z + v.w * v.w;
#pragma unroll
    for (int o = 16; o > 0; o >>= 1)
        ss += __shfl_down_sync(0xffffffffu, ss, o);
    __shared__ float warp_s[8];
    if ((threadIdx.x & 31) == 0) warp_s[threadIdx.x >> 5] = ss;
    __syncthreads();
    if (threadIdx.x < 8) {
        float t = warp_s[threadIdx.x];
#pragma unroll
        for (int o = 4; o > 0; o >>= 1)
            t += __shfl_down_sync(0xffu, t, o);
        if (threadIdx.x == 0) warp_s[0] = t;
    }
    __syncthreads();
    float scale = 1.f / fmaxf(sqrtf(warp_s[0]), EPS);
    v.x *= scale; v.y *= scale; v.z *= scale; v.w *= scale;
    row[threadIdx.x] = v;
}

// ---------------------------------------------------------------------------
// MV GEMM (mma.sync bf16 split hi/lo, 3-stage cp.async) + fused L2 norm.
// CTA 128x128, BK=64. 8 warps (2x4). Last N-CTA per row-block normalizes.
// ---------------------------------------------------------------------------
#define NCH 16
#define STG 65536
#define NSTG 3

__device__ __forceinline__ void stage_load(uint32_t smb, int s, int ch,
                                           int m0, int n0, int tid) {
    const int kt = ch * 64;
    const __nv_bfloat16* srcs[4] = {g_Ahi, g_Alo, g_Whi, g_Wlo};
    const int row0s[4] = {m0, m0, n0, n0};
#pragma unroll
    for (int t4 = 0; t4 < 4; t4++) {
        const __nv_bfloat16* src = srcs[t4];
        const int row0 = row0s[t4];
        const uint32_t tb = smb + s * STG + t4 * 16384;
#pragma unroll
        for (int it = 0; it < 4; it++) {
            int q = tid + it * 256;
            int r = q >> 3, c16 = q & 7;
            const void* g = src + (size_t)(row0 + r) * H_ + kt + c16 * 8;
            uint32_t d = tb + (uint32_t)(r * 128 + ((c16 ^ (r & 7)) << 4));
            CP16(d, g);
        }
    }
}

__global__ __launch_bounds__(256, 1)
void mv_gemm_mma(const float* __restrict__ bias,
                 const float* __restrict__ mask,
                 float* __restrict__ C) {
    extern __shared__ char sm[];
    const uint32_t smb = smem_u32(sm);
    __shared__ int lastflag;

    const int tid = threadIdx.x;
    const int wid = tid >> 5, lane = tid & 31;
    const int warp_m = wid & 1;
    const int warp_n = wid >> 1;
    const int m0 = blockIdx.y * 128, n0 = blockIdx.x * 128;

    float acc[4][4][4];
#pragma unroll
    for (int i = 0; i < 4; i++)
#pragma unroll
        for (int j = 0; j < 4; j++)
#pragma unroll
            for (int k = 0; k < 4; k++) acc[i][j][k] = 0.f;

    const int g8 = lane >> 3, i8 = lane & 7;
    const int a_r = warp_m * 64 + (g8 & 1) * 8 + i8;
    const int a_cadd = g8 >> 1;
    const int b_r = warp_n * 32 + (g8 >> 1) * 8 + i8;
    const int b_cadd = g8 & 1;

    stage_load(smb, 0, 0, m0, n0, tid);
    CP_COMMIT();
    stage_load(smb, 1, 1, m0, n0, tid);
    CP_COMMIT();

    for (int ch = 0; ch < NCH; ch++) {
        const int s = ch % NSTG;
        if (ch + 2 < NCH) {
            stage_load(smb, (ch + 2) % NSTG, ch + 2, m0, n0, tid);
            CP_COMMIT();
            CP_WAIT2();
        } else if (ch + 1 < NCH) {
            CP_WAIT1();
        } else {
            CP_WAIT0();
        }
        __syncthreads();

        const uint32_t ah = smb + s * STG;
        const uint32_t al = ah + 16384;
        const uint32_t wh = ah + 32768;
        const uint32_t wl = ah + 49152;

#pragma unroll
        for (int ks = 0; ks < 4; ks++) {
            uint32_t Ahi[4][4], Alo[4][4];
#pragma unroll
            for (int mt = 0; mt < 4; mt++) {
                int r = a_r + mt * 16;
                int c16 = ks * 2 + a_cadd;
                uint32_t off = (uint32_t)(r * 128 + ((c16 ^ (r & 7)) << 4));
                LDSM_X4(Ahi[mt][0], Ahi[mt][1], Ahi[mt][2], Ahi[mt][3], ah + off);
                LDSM_X4(Alo[mt][0], Alo[mt][1], Alo[mt][2], Alo[mt][3], al + off);
            }
            uint32_t Bhi[4][2], Blo[4][2];
#pragma unroll
            for (int bh = 0; bh < 2; bh++) {
                int r = b_r + bh * 16;
                int c16 = ks * 2 + b_cadd;
                uint32_t off = (uint32_t)(r * 128 + ((c16 ^ (r & 7)) << 4));
                uint32_t t0, t1, t2, t3;
                LDSM_X4(t0, t1, t2, t3, wh + off);
                Bhi[2 * bh][0] = t0; Bhi[2 * bh][1] = t1;
                Bhi[2 * bh + 1][0] = t2; Bhi[2 * bh + 1][1] = t3;
                LDSM_X4(t0, t1, t2, t3, wl + off);
                Blo[2 * bh][0] = t0; Blo[2 * bh][1] = t1;
                Blo[2 * bh + 1][0] = t2; Blo[2 * bh + 1][1] = t3;
            }
#pragma unroll
            for (int mt = 0; mt < 4; mt++)
#pragma unroll
                for (int ng = 0; ng < 4; ng++) {
                    MMA16816(acc[mt][ng], Ahi[mt], Bhi[ng]);
                    MMA16816(acc[mt][ng], Ahi[mt], Blo[ng]);
                    MMA16816(acc[mt][ng], Alo[mt], Bhi[ng]);
                }
        }
        __syncthreads();
    }

    // ---- epilogue: bias + mask, store, per-row sumsq ----
    float* rowss = reinterpret_cast<float*>(sm);     // stages are dead now
    if (tid < 128) rowss[tid] = 0.f;
    __syncthreads();

#pragma unroll
    for (int mt = 0; mt < 4; mt++) {
        const int lr0 = warp_m * 64 + mt * 16 + (lane >> 2);
        const int r0 = m0 + lr0;
        const float mk0 = mask[r0];
        const float mk1 = mask[r0 + 8];
        float ss0 = 0.f, ss1 = 0.f;
#pragma unroll
        for (int ng = 0; ng < 4; ng++) {
            const int c = n0 + warp_n * 32 + ng * 8 + 2 * (lane & 3);
            const float2 b2 = *reinterpret_cast<const float2*>(bias + c);
            float2 o0, o1;
            o0.x = (acc[mt][ng][0] + b2.x) * mk0;
            o0.y = (acc[mt][ng][1] + b2.y) * mk0;
            o1.x = (acc[mt][ng][2] + b2.x) * mk1;
            o1.y = (acc[mt][ng][3] + b2.y) * mk1;
            ss0 += o0.x * o0.x + o0.y * o0.y;
            ss1 += o1.x * o1.x + o1.y * o1.y;
            *reinterpret_cast<float2*>(C + (size_t)r0 * H_ + c) = o0;
            *reinterpret_cast<float2*>(C + (size_t)(r0 + 8) * H_ + c) = o1;
        }
        // reduce across the 4 lanes sharing this row
        ss0 += __shfl_xor_sync(0xffffffffu, ss0, 1);
        ss0 += __shfl_xor_sync(0xffffffffu, ss0, 2);
        ss1 += __shfl_xor_sync(0xffffffffu, ss1, 1);
        ss1 += __shfl_xor_sync(0xffffffffu, ss1, 2);
        if ((lane & 3) == 0) {
            atomicAdd(&rowss[lr0], ss0);
            atomicAdd(&rowss[lr0 + 8], ss1);
        }
    }
    __syncthreads();
    if (tid < 128) atomicAdd(&g_rowss[m0 + tid], rowss[tid]);
    __threadfence();
    __syncthreads();
    if (tid == 0) {
        int old = atomicAdd(&g_rowcnt[blockIdx.y], 1);
        lastflag = (old == (int)gridDim.x - 1);
    }
    __syncthreads();

    if (lastflag) {
        __threadfence();                     // acquire peer CTAs' C stores
        // warp w normalizes rows w*16 .. w*16+15 of this 128-row block
        for (int i = 0; i < 16; i++) {
            const int m = m0 + wid * 16 + i;
            const float sc = 1.f / fmaxf(sqrtf(g_rowss[m]), EPS);
            float4* c4 = reinterpret_cast<float4*>(C + (size_t)m * H_);
#pragma unroll
            for (int j = 0; j < 8; j++) {
                float4 v = c4[j * 32 + lane];
                v.x *= sc; v.y *= sc; v.z *= sc; v.w *= sc;
                c4[j * 32 + lane] = v;
            }
        }
    }
}

// ---------------------------------------------------------------------------
extern "C" void kernel_launch(void* const* d_in, const int* in_sizes, int n_in,
                              void* d_out, int out_size) {
    const float* hidden   = (const float*)d_in[0];
    const int*   ids      = (const int*)d_in[1];
    const float* attn     = (const float*)d_in[2];
    const float* dense_w  = (const float*)d_in[3];
    const float* dense_b  = (const float*)d_in[4];
    const float* sparse_w = (const float*)d_in[5];
    const float* sparse_b = (const float*)d_in[6];
    const float* mv_w     = (const float*)d_in[7];
    const float* mv_b     = (const float*)d_in[8];

    float* out        = (float*)d_out;
    float* out_dense  = out + OFF_DENSE;
    float* out_sparse = out + OFF_SPARSE;
    float* out_mv     = out + OFF_MV;

    __nv_bfloat16 *whi, *wlo;
    cudaGetSymbolAddress((void**)&whi, g_Whi);
    cudaGetSymbolAddress((void**)&wlo, g_Wlo);

    // 1. zero sparse region + accumulators + counters
    zero_kernel<<<2048, 256>>>(out_sparse);

    // 2. mega pass: split hidden + pooled partials + sparse dots + masksum
    {
        dim3 g(B_, S_ / SCH);   // (32, 16)
        mega_pass<<<g, 256>>>(hidden, attn, sparse_w);
    }

    // 3. split W into bf16 hi/lo
    split_bf16_kernel<<<1024, 256>>>((const float4*)mv_w,
                                     (__nv_bfloat162*)whi,
                                     (__nv_bfloat162*)wlo, H_ * H_ / 4);

    // 4. MV GEMM + fused per-row L2 norm   (4th launch -> gets profiled)
    {
        const int smem_bytes = NSTG * STG;  // 196608
        cudaFuncSetAttribute(mv_gemm_mma,
                             cudaFuncAttributeMaxDynamicSharedMemorySize,
                             smem_bytes);
        dim3 g(H_ / 128, TOK / 128);        // (8, 128)
        mv_gemm_mma<<<g, 256, smem_bytes>>>(mv_b, attn, out_mv);
    }

    // 5. sparse finalize
    sparse_finalize<<<TOK / 256, 256>>>(attn, sparse_b, ids, out_sparse);

    // 6. dense head + its L2 norm
    dense_kernel2<<<H_ / 8, 256>>>(dense_w, dense_b, out_dense);
    l2norm_kernel<<<B_, 256>>>(out_dense);
}

// round 9
// speedup vs baseline: 1.1755x; 1.1755x over previous
#include <cuda_runtime.h>
#include <cuda_bf16.h>
#include <cstdint>

#define B_  32
#define S_  512
#define H_  1024
#define V_  250002

#define TOK (B_ * S_)          // 16384
#define OFF_DENSE  0
#define OFF_SPARSE (B_ * H_)                 // 32768
#define OFF_MV     (OFF_SPARSE + B_ * V_)    // 8032832

#define EPS 1e-12f

// ---------------------------------------------------------------------------
// Device-global scratch (allocation-free rule)
// ---------------------------------------------------------------------------
__device__ float g_pooled[B_ * H_];
__device__ float g_masksum[B_];
__device__ float g_tokdot[TOK];
__device__ __align__(16) __nv_bfloat16 g_Ahi[TOK * H_];
__device__ __align__(16) __nv_bfloat16 g_Alo[TOK * H_];
__device__ __align__(16) __nv_bfloat16 g_Whi[H_ * H_];
__device__ __align__(16) __nv_bfloat16 g_Wlo[H_ * H_];

// ---------------------------------------------------------------------------
// PTX helpers
// ---------------------------------------------------------------------------
__device__ __forceinline__ uint32_t smem_u32(const void* p) {
    uint32_t a;
    asm("{ .reg .u64 t; cvta.to.shared.u64 t, %1; cvt.u32.u64 %0, t; }"
        : "=r"(a) : "l"(p));
    return a;
}
#define CP16(dst, src) \
    asm volatile("cp.async.cg.shared.global [%0], [%1], 16;" \
                 :: "r"(dst), "l"(src) : "memory")
#define CP_COMMIT() asm volatile("cp.async.commit_group;" ::: "memory")
#define CP_WAIT2()  asm volatile("cp.async.wait_group 2;" ::: "memory")
#define CP_WAIT1()  asm volatile("cp.async.wait_group 1;" ::: "memory")
#define CP_WAIT0()  asm volatile("cp.async.wait_group 0;" ::: "memory")
#define LDSM_X4(r0, r1, r2, r3, addr) \
    asm volatile("ldmatrix.sync.aligned.m8n8.x4.shared.b16 {%0,%1,%2,%3}, [%4];" \
                 : "=r"(r0), "=r"(r1), "=r"(r2), "=r"(r3) : "r"(addr))
#define MMA16816(d, a, b) \
    asm volatile("mma.sync.aligned.m16n8k16.row.col.f32.bf16.bf16.f32 " \
                 "{%0,%1,%2,%3}, {%4,%5,%6,%7}, {%8,%9}, {%0,%1,%2,%3};" \
                 : "+f"((d)[0]), "+f"((d)[1]), "+f"((d)[2]), "+f"((d)[3]) \
                 : "r"((a)[0]), "r"((a)[1]), "r"((a)[2]), "r"((a)[3]), \
                   "r"((b)[0]), "r"((b)[1]))

// ---------------------------------------------------------------------------
// Zero sparse output region + pooled accumulator + masksum
// ---------------------------------------------------------------------------
__global__ void zero_kernel(float* __restrict__ sparse) {
    const int gsz = gridDim.x * blockDim.x;
    const int gtid = blockIdx.x * blockDim.x + threadIdx.x;
    float4 z = make_float4(0.f, 0.f, 0.f, 0.f);

    float4* p = reinterpret_cast<float4*>(sparse);
    for (int i = gtid; i < (B_ * V_) / 4; i += gsz) p[i] = z;

    float4* pp = reinterpret_cast<float4*>(g_pooled);
    for (int i = gtid; i < B_ * H_ / 4; i += gsz) pp[i] = z;

    if (gtid < B_) g_masksum[gtid] = 0.f;
}

// ---------------------------------------------------------------------------
// MEGA PASS: one read of hidden does (a) bf16 hi/lo split, (b) masked-pool
// partial accumulation (atomics), (c) per-token sparse dot, (d) masksum.
// grid: (B_, S_/32). block: 256 (thread t owns h = 4t..4t+3).
// ---------------------------------------------------------------------------
#define SCH 32
__global__ __launch_bounds__(256, 4)
void mega_pass(const float* __restrict__ x,
               const float* __restrict__ mask,
               const float* __restrict__ sw) {
    const int b = blockIdx.x;
    const int s0 = blockIdx.y * SCH;
    const int tid = threadIdx.x;
    const int wid = tid >> 5, lane = tid & 31;

    __shared__ float msk[SCH];
    __shared__ float red[SCH][8];
    if (tid < SCH) msk[tid] = mask[b * S_ + s0 + tid];
    const float4 w4 = *reinterpret_cast<const float4*>(sw + tid * 4);
    __syncthreads();

    if (wid == 0) {
        float mv = msk[lane];
#pragma unroll
        for (int o = 16; o > 0; o >>= 1)
            mv += __shfl_down_sync(0xffffffffu, mv, o);
        if (lane == 0) atomicAdd(&g_masksum[b], mv);
    }

    float p0 = 0.f, p1 = 0.f, p2 = 0.f, p3 = 0.f;
    __nv_bfloat162* ahi = reinterpret_cast<__nv_bfloat162*>(g_Ahi);
    __nv_bfloat162* alo = reinterpret_cast<__nv_bfloat162*>(g_Alo);

#pragma unroll 4
    for (int si = 0; si < SCH; si++) {
        const int t = b * S_ + s0 + si;
        const float4 v = *reinterpret_cast<const float4*>(
            x + (size_t)t * H_ + tid * 4);
        __nv_bfloat162 h01 = __floats2bfloat162_rn(v.x, v.y);
        __nv_bfloat162 h23 = __floats2bfloat162_rn(v.z, v.w);
        float2 f01 = __bfloat1622float2(h01);
        float2 f23 = __bfloat1622float2(h23);
        __nv_bfloat162 l01 = __floats2bfloat162_rn(v.x - f01.x, v.y - f01.y);
        __nv_bfloat162 l23 = __floats2bfloat162_rn(v.z - f23.x, v.w - f23.y);
        const size_t o2 = (size_t)t * (H_ / 2) + tid * 2;
        ahi[o2] = h01; ahi[o2 + 1] = h23;
        alo[o2] = l01; alo[o2 + 1] = l23;
        const float mk = msk[si];
        p0 += v.x * mk; p1 += v.y * mk; p2 += v.z * mk; p3 += v.w * mk;
        float d = v.x * w4.x + v.y * w4.y + v.z * w4.z + v.w * w4.w;
#pragma unroll
        for (int o = 16; o > 0; o >>= 1)
            d += __shfl_down_sync(0xffffffffu, d, o);
        if (lane == 0) red[si][wid] = d;
    }
    __syncthreads();
    {
        const int si = tid >> 3, j = tid & 7;
        float d = red[si][j];
        d += __shfl_down_sync(0xffffffffu, d, 4);
        d += __shfl_down_sync(0xffffffffu, d, 2);
        d += __shfl_down_sync(0xffffffffu, d, 1);
        if (j == 0) g_tokdot[b * S_ + s0 + si] = d;
    }
    float* pp = g_pooled + b * H_ + tid * 4;
    atomicAdd(pp + 0, p0);
    atomicAdd(pp + 1, p1);
    atomicAdd(pp + 2, p2);
    atomicAdd(pp + 3, p3);
}

// ---------------------------------------------------------------------------
// Sparse finalize
// ---------------------------------------------------------------------------
__global__ void sparse_finalize(const float* __restrict__ mask,
                                const float* __restrict__ sb,
                                const int* __restrict__ ids,
                                float* __restrict__ sparse) {
    const int t = blockIdx.x * 256 + threadIdx.x;
    float tw = (g_tokdot[t] + sb[0]) * mask[t];
    if (tw > 0.f) {
        const int b = t / S_;
        const int id = ids[t];
        if (id >= 0 && id < V_)
            atomicAdd(sparse + (size_t)b * V_ + id, tw);
    }
}

// ---------------------------------------------------------------------------
// Split fp32 -> bf16 hi/lo (mv_w)
// ---------------------------------------------------------------------------
__global__ void split_bf16_kernel(const float4* __restrict__ src,
                                  __nv_bfloat162* __restrict__ hi,
                                  __nv_bfloat162* __restrict__ lo, int n4) {
    for (int i = blockIdx.x * blockDim.x + threadIdx.x; i < n4;
         i += gridDim.x * blockDim.x) {
        float4 v = src[i];
        __nv_bfloat162 h01 = __floats2bfloat162_rn(v.x, v.y);
        __nv_bfloat162 h23 = __floats2bfloat162_rn(v.z, v.w);
        float2 f01 = __bfloat1622float2(h01);
        float2 f23 = __bfloat1622float2(h23);
        __nv_bfloat162 l01 = __floats2bfloat162_rn(v.x - f01.x, v.y - f01.y);
        __nv_bfloat162 l23 = __floats2bfloat162_rn(v.z - f23.x, v.w - f23.y);
        hi[i * 2 + 0] = h01;  hi[i * 2 + 1] = h23;
        lo[i * 2 + 0] = l01;  lo[i * 2 + 1] = l23;
    }
}

// ---------------------------------------------------------------------------
// Dense head
// ---------------------------------------------------------------------------
__global__ __launch_bounds__(256, 4)
void dense_kernel2(const float* __restrict__ dw,
                   const float* __restrict__ db,
                   float* __restrict__ out) {
    __shared__ float ws[8][H_ + 1];
    const int tid = threadIdx.x;
    const int h0 = blockIdx.x * 8;
#pragma unroll
    for (int i = 0; i < 32; i++) {
        int idx = tid + i * 256;
        int r = idx >> 10, c = idx & 1023;
        ws[r][c] = dw[(size_t)(h0 + r) * H_ + c];
    }
    __syncthreads();
    const int b = tid >> 3;
    const int hi = tid & 7;
    const float* p = g_pooled + b * H_;
    float acc = 0.f;
#pragma unroll 8
    for (int k = 0; k < H_; k++) acc += p[k] * ws[hi][k];
    const float pinv = 1.f / g_masksum[b];
    out[b * H_ + h0 + hi] = tanhf(acc * pinv + db[h0 + hi]);
}

// ---------------------------------------------------------------------------
// Row L2-normalize in place (rows of H_=1024)
// ---------------------------------------------------------------------------
__global__ void l2norm_kernel(float* __restrict__ data) {
    float4* row = reinterpret_cast<float4*>(data + (size_t)blockIdx.x * H_);
    float4 v = row[threadIdx.x];
    float ss = v.x * v.x + v.y * v.y + v.z * v.z + v.w * v.w;
#pragma unroll
    for (int o = 16; o > 0; o >>= 1)
        ss += __shfl_down_sync(0xffffffffu, ss, o);
    __shared__ float warp_s[8];
    if ((threadIdx.x & 31) == 0) warp_s[threadIdx.x >> 5] = ss;
    __syncthreads();
    if (threadIdx.x < 8) {
        float t = warp_s[threadIdx.x];
#pragma unroll
        for (int o = 4; o > 0; o >>= 1)
            t += __shfl_down_sync(0xffu, t, o);
        if (threadIdx.x == 0) warp_s[0] = t;
    }
    __syncthreads();
    float scale = 1.f / fmaxf(sqrtf(warp_s[0]), EPS);
    v.x *= scale; v.y *= scale; v.z *= scale; v.w *= scale;
    row[threadIdx.x] = v;
}

// ---------------------------------------------------------------------------
// MV GEMM via mma.sync bf16 (split hi/lo, 3 passes), 3-stage cp.async.
// CTA 128x128, BK=64. 16 warps (4x4), warp tile 32x32 -> low reg pressure,
// 4 warps/SMSP for latency hiding.
// Stage (65536 B): Ahi @0, Alo @16384, Whi @32768, Wlo @49152.
// ---------------------------------------------------------------------------
#define NCH 16
#define STG 65536
#define NSTG 3
#define GT 512

__device__ __forceinline__ void stage_load(uint32_t smb, int s, int ch,
                                           int m0, int n0, int tid) {
    const int kt = ch * 64;
    const __nv_bfloat16* srcs[4] = {g_Ahi, g_Alo, g_Whi, g_Wlo};
    const int row0s[4] = {m0, m0, n0, n0};
#pragma unroll
    for (int t4 = 0; t4 < 4; t4++) {
        const __nv_bfloat16* src = srcs[t4];
        const int row0 = row0s[t4];
        const uint32_t tb = smb + s * STG + t4 * 16384;
#pragma unroll
        for (int it = 0; it < 2; it++) {
            int q = tid + it * GT;           // 0..1023
            int r = q >> 3, c16 = q & 7;
            const void* g = src + (size_t)(row0 + r) * H_ + kt + c16 * 8;
            uint32_t d = tb + (uint32_t)(r * 128 + ((c16 ^ (r & 7)) << 4));
            CP16(d, g);
        }
    }
}

__global__ __launch_bounds__(GT, 1)
void mv_gemm_mma(const float* __restrict__ bias,
                 const float* __restrict__ mask,
                 float* __restrict__ C) {
    extern __shared__ char sm[];
    const uint32_t smb = smem_u32(sm);

    const int tid = threadIdx.x;
    const int wid = tid >> 5, lane = tid & 31;
    const int warp_m = wid & 3;        // 0..3 -> 32-row group
    const int warp_n = wid >> 2;       // 0..3 -> 32-col group
    const int m0 = blockIdx.y * 128, n0 = blockIdx.x * 128;

    float acc[2][4][4];
#pragma unroll
    for (int i = 0; i < 2; i++)
#pragma unroll
        for (int j = 0; j < 4; j++)
#pragma unroll
            for (int k = 0; k < 4; k++) acc[i][j][k] = 0.f;

    const int g8 = lane >> 3, i8 = lane & 7;
    const int a_r = warp_m * 32 + (g8 & 1) * 8 + i8;
    const int a_cadd = g8 >> 1;
    const int b_r = warp_n * 32 + (g8 >> 1) * 8 + i8;
    const int b_cadd = g8 & 1;

    stage_load(smb, 0, 0, m0, n0, tid);
    CP_COMMIT();
    stage_load(smb, 1, 1, m0, n0, tid);
    CP_COMMIT();

    for (int ch = 0; ch < NCH; ch++) {
        const int s = ch % NSTG;
        if (ch + 2 < NCH) {
            stage_load(smb, (ch + 2) % NSTG, ch + 2, m0, n0, tid);
            CP_COMMIT();
            CP_WAIT2();
        } else if (ch + 1 < NCH) {
            CP_WAIT1();
        } else {
            CP_WAIT0();
        }
        __syncthreads();

        const uint32_t ah = smb + s * STG;
        const uint32_t al = ah + 16384;
        const uint32_t wh = ah + 32768;
        const uint32_t wl = ah + 49152;

#pragma unroll
        for (int ks = 0; ks < 4; ks++) {
            uint32_t Ahi[2][4], Alo[2][4];
#pragma unroll
            for (int mt = 0; mt < 2; mt++) {
                int r = a_r + mt * 16;
                int c16 = ks * 2 + a_cadd;
                uint32_t off = (uint32_t)(r * 128 + ((c16 ^ (r & 7)) << 4));
                LDSM_X4(Ahi[mt][0], Ahi[mt][1], Ahi[mt][2], Ahi[mt][3], ah + off);
                LDSM_X4(Alo[mt][0], Alo[mt][1], Alo[mt][2], Alo[mt][3], al + off);
            }
            uint32_t Bhi[4][2], Blo[4][2];
#pragma unroll
            for (int bh = 0; bh < 2; bh++) {
                int r = b_r + bh * 16;
                int c16 = ks * 2 + b_cadd;
                uint32_t off = (uint32_t)(r * 128 + ((c16 ^ (r & 7)) << 4));
                uint32_t t0, t1, t2, t3;
                LDSM_X4(t0, t1, t2, t3, wh + off);
                Bhi[2 * bh][0] = t0; Bhi[2 * bh][1] = t1;
                Bhi[2 * bh + 1][0] = t2; Bhi[2 * bh + 1][1] = t3;
                LDSM_X4(t0, t1, t2, t3, wl + off);
                Blo[2 * bh][0] = t0; Blo[2 * bh][1] = t1;
                Blo[2 * bh + 1][0] = t2; Blo[2 * bh + 1][1] = t3;
            }
#pragma unroll
            for (int mt = 0; mt < 2; mt++)
#pragma unroll
                for (int ng = 0; ng < 4; ng++) {
                    MMA16816(acc[mt][ng], Ahi[mt], Bhi[ng]);
                    MMA16816(acc[mt][ng], Ahi[mt], Blo[ng]);
                    MMA16816(acc[mt][ng], Alo[mt], Bhi[ng]);
                }
        }
        __syncthreads();
    }

    // epilogue: + bias, * mask, store float2 pairs
#pragma unroll
    for (int mt = 0; mt < 2; mt++) {
        const int r0 = m0 + warp_m * 32 + mt * 16 + (lane >> 2);
        const float mk0 = mask[r0];
        const float mk1 = mask[r0 + 8];
#pragma unroll
        for (int ng = 0; ng < 4; ng++) {
            const int c = n0 + warp_n * 32 + ng * 8 + 2 * (lane & 3);
            const float2 b2 = *reinterpret_cast<const float2*>(bias + c);
            float2 o0, o1;
            o0.x = (acc[mt][ng][0] + b2.x) * mk0;
            o0.y = (acc[mt][ng][1] + b2.y) * mk0;
            o1.x = (acc[mt][ng][2] + b2.x) * mk1;
            o1.y = (acc[mt][ng][3] + b2.y) * mk1;
            *reinterpret_cast<float2*>(C + (size_t)r0 * H_ + c) = o0;
            *reinterpret_cast<float2*>(C + (size_t)(r0 + 8) * H_ + c) = o1;
        }
    }
}

// ---------------------------------------------------------------------------
extern "C" void kernel_launch(void* const* d_in, const int* in_sizes, int n_in,
                              void* d_out, int out_size) {
    const float* hidden   = (const float*)d_in[0];
    const int*   ids      = (const int*)d_in[1];
    const float* attn     = (const float*)d_in[2];
    const float* dense_w  = (const float*)d_in[3];
    const float* dense_b  = (const float*)d_in[4];
    const float* sparse_w = (const float*)d_in[5];
    const float* sparse_b = (const float*)d_in[6];
    const float* mv_w     = (const float*)d_in[7];
    const float* mv_b     = (const float*)d_in[8];

    float* out        = (float*)d_out;
    float* out_dense  = out + OFF_DENSE;
    float* out_sparse = out + OFF_SPARSE;
    float* out_mv     = out + OFF_MV;

    __nv_bfloat16 *whi, *wlo;
    cudaGetSymbolAddress((void**)&whi, g_Whi);
    cudaGetSymbolAddress((void**)&wlo, g_Wlo);

    // 1. zero sparse region + accumulators
    zero_kernel<<<2048, 256>>>(out_sparse);

    // 2. mega pass: split hidden + pooled partials + sparse dots + masksum
    {
        dim3 g(B_, S_ / SCH);   // (32, 16)
        mega_pass<<<g, 256>>>(hidden, attn, sparse_w);
    }

    // 3. split W into bf16 hi/lo
    split_bf16_kernel<<<1024, 256>>>((const float4*)mv_w,
                                     (__nv_bfloat162*)whi,
                                     (__nv_bfloat162*)wlo, H_ * H_ / 4);

    // 4. MV GEMM (mma.sync, 16 warps, 3-stage)   (4th launch -> profiled)
    {
        const int smem_bytes = NSTG * STG;  // 196608
        cudaFuncSetAttribute(mv_gemm_mma,
                             cudaFuncAttributeMaxDynamicSharedMemorySize,
                             smem_bytes);
        dim3 g(H_ / 128, TOK / 128);        // (8, 128)
        mv_gemm_mma<<<g, GT, smem_bytes>>>(mv_b, attn, out_mv);
    }

    // 5. MV per-token L2 norm
    l2norm_kernel<<<TOK, 256>>>(out_mv);

    // 6. sparse finalize
    sparse_finalize<<<TOK / 256, 256>>>(attn, sparse_b, ids, out_sparse);

    // 7. dense head + its L2 norm
    dense_kernel2<<<H_ / 8, 256>>>(dense_w, dense_b, out_dense);
    l2norm_kernel<<<B_, 256>>>(out_dense);
}

// round 11
// speedup vs baseline: 1.2924x; 1.0994x over previous
#include <cuda_runtime.h>
#include <cuda_bf16.h>
#include <cstdint>

#define B_  32
#define S_  512
#define H_  1024
#define V_  250002

#define TOK (B_ * S_)          // 16384
#define OFF_DENSE  0
#define OFF_SPARSE (B_ * H_)                 // 32768
#define OFF_MV     (OFF_SPARSE + B_ * V_)    // 8032832

#define EPS 1e-12f

// ---------------------------------------------------------------------------
// Device-global scratch (allocation-free rule)
// ---------------------------------------------------------------------------
__device__ float g_pooled[B_ * H_];
__device__ float g_masksum[B_];
__device__ float g_tokdot[TOK];
__device__ __align__(16) __nv_bfloat16 g_Ahi[TOK * H_];
__device__ __align__(16) __nv_bfloat16 g_Alo[TOK * H_];
__device__ __align__(16) __nv_bfloat16 g_Whi[H_ * H_];
__device__ __align__(16) __nv_bfloat16 g_Wlo[H_ * H_];

// ---------------------------------------------------------------------------
// PTX helpers
// ---------------------------------------------------------------------------
__device__ __forceinline__ uint32_t smem_u32(const void* p) {
    uint32_t a;
    asm("{ .reg .u64 t; cvta.to.shared.u64 t, %1; cvt.u32.u64 %0, t; }"
        : "=r"(a) : "l"(p));
    return a;
}
#define CP16(dst, src) \
    asm volatile("cp.async.cg.shared.global [%0], [%1], 16;" \
                 :: "r"(dst), "l"(src) : "memory")
#define CP_COMMIT() asm volatile("cp.async.commit_group;" ::: "memory")
#define CP_WAIT2()  asm volatile("cp.async.wait_group 2;" ::: "memory")
#define CP_WAIT1()  asm volatile("cp.async.wait_group 1;" ::: "memory")
#define CP_WAIT0()  asm volatile("cp.async.wait_group 0;" ::: "memory")
#define LDSM_X4(r0, r1, r2, r3, addr) \
    asm volatile("ldmatrix.sync.aligned.m8n8.x4.shared.b16 {%0,%1,%2,%3}, [%4];" \
                 : "=r"(r0), "=r"(r1), "=r"(r2), "=r"(r3) : "r"(addr))
#define MMA16816(d, a, b) \
    asm volatile("mma.sync.aligned.m16n8k16.row.col.f32.bf16.bf16.f32 " \
                 "{%0,%1,%2,%3}, {%4,%5,%6,%7}, {%8,%9}, {%0,%1,%2,%3};" \
                 : "+f"((d)[0]), "+f"((d)[1]), "+f"((d)[2]), "+f"((d)[3]) \
                 : "r"((a)[0]), "r"((a)[1]), "r"((a)[2]), "r"((a)[3]), \
                   "r"((b)[0]), "r"((b)[1]))

// ---------------------------------------------------------------------------
// Zero sparse output region + pooled accumulator + masksum
// ---------------------------------------------------------------------------
__global__ void zero_kernel(float* __restrict__ sparse) {
    const int gsz = gridDim.x * blockDim.x;
    const int gtid = blockIdx.x * blockDim.x + threadIdx.x;
    float4 z = make_float4(0.f, 0.f, 0.f, 0.f);

    float4* p = reinterpret_cast<float4*>(sparse);
    for (int i = gtid; i < (B_ * V_) / 4; i += gsz) p[i] = z;

    float4* pp = reinterpret_cast<float4*>(g_pooled);
    for (int i = gtid; i < B_ * H_ / 4; i += gsz) pp[i] = z;

    if (gtid < B_) g_masksum[gtid] = 0.f;
}

// ---------------------------------------------------------------------------
// MEGA PASS: one read of hidden does (a) bf16 hi/lo split, (b) masked-pool
// partial accumulation (atomics), (c) per-token sparse dot, (d) masksum.
// grid: (B_, S_/32). block: 256 (thread t owns h = 4t..4t+3).
// ---------------------------------------------------------------------------
#define SCH 32
__global__ __launch_bounds__(256, 4)
void mega_pass(const float* __restrict__ x,
               const float* __restrict__ mask,
               const float* __restrict__ sw) {
    const int b = blockIdx.x;
    const int s0 = blockIdx.y * SCH;
    const int tid = threadIdx.x;
    const int wid = tid >> 5, lane = tid & 31;

    __shared__ float msk[SCH];
    __shared__ float red[SCH][8];
    if (tid < SCH) msk[tid] = mask[b * S_ + s0 + tid];
    const float4 w4 = *reinterpret_cast<const float4*>(sw + tid * 4);
    __syncthreads();

    if (wid == 0) {
        float mv = msk[lane];
#pragma unroll
        for (int o = 16; o > 0; o >>= 1)
            mv += __shfl_down_sync(0xffffffffu, mv, o);
        if (lane == 0) atomicAdd(&g_masksum[b], mv);
    }

    float p0 = 0.f, p1 = 0.f, p2 = 0.f, p3 = 0.f;
    __nv_bfloat162* ahi = reinterpret_cast<__nv_bfloat162*>(g_Ahi);
    __nv_bfloat162* alo = reinterpret_cast<__nv_bfloat162*>(g_Alo);

#pragma unroll 4
    for (int si = 0; si < SCH; si++) {
        const int t = b * S_ + s0 + si;
        const float4 v = *reinterpret_cast<const float4*>(
            x + (size_t)t * H_ + tid * 4);
        __nv_bfloat162 h01 = __floats2bfloat162_rn(v.x, v.y);
        __nv_bfloat162 h23 = __floats2bfloat162_rn(v.z, v.w);
        float2 f01 = __bfloat1622float2(h01);
        float2 f23 = __bfloat1622float2(h23);
        __nv_bfloat162 l01 = __floats2bfloat162_rn(v.x - f01.x, v.y - f01.y);
        __nv_bfloat162 l23 = __floats2bfloat162_rn(v.z - f23.x, v.w - f23.y);
        const size_t o2 = (size_t)t * (H_ / 2) + tid * 2;
        ahi[o2] = h01; ahi[o2 + 1] = h23;
        alo[o2] = l01; alo[o2 + 1] = l23;
        const float mk = msk[si];
        p0 += v.x * mk; p1 += v.y * mk; p2 += v.z * mk; p3 += v.w * mk;
        float d = v.x * w4.x + v.y * w4.y + v.z * w4.z + v.w * w4.w;
#pragma unroll
        for (int o = 16; o > 0; o >>= 1)
            d += __shfl_down_sync(0xffffffffu, d, o);
        if (lane == 0) red[si][wid] = d;
    }
    __syncthreads();
    {
        const int si = tid >> 3, j = tid & 7;
        float d = red[si][j];
        d += __shfl_down_sync(0xffffffffu, d, 4);
        d += __shfl_down_sync(0xffffffffu, d, 2);
        d += __shfl_down_sync(0xffffffffu, d, 1);
        if (j == 0) g_tokdot[b * S_ + s0 + si] = d;
    }
    float* pp = g_pooled + b * H_ + tid * 4;
    atomicAdd(pp + 0, p0);
    atomicAdd(pp + 1, p1);
    atomicAdd(pp + 2, p2);
    atomicAdd(pp + 3, p3);
}

// ---------------------------------------------------------------------------
// Sparse finalize
// ---------------------------------------------------------------------------
__global__ void sparse_finalize(const float* __restrict__ mask,
                                const float* __restrict__ sb,
                                const int* __restrict__ ids,
                                float* __restrict__ sparse) {
    const int t = blockIdx.x * 256 + threadIdx.x;
    float tw = (g_tokdot[t] + sb[0]) * mask[t];
    if (tw > 0.f) {
        const int b = t / S_;
        const int id = ids[t];
        if (id >= 0 && id < V_)
            atomicAdd(sparse + (size_t)b * V_ + id, tw);
    }
}

// ---------------------------------------------------------------------------
// Split fp32 -> bf16 hi/lo (mv_w)
// ---------------------------------------------------------------------------
__global__ void split_bf16_kernel(const float4* __restrict__ src,
                                  __nv_bfloat162* __restrict__ hi,
                                  __nv_bfloat162* __restrict__ lo, int n4) {
    for (int i = blockIdx.x * blockDim.x + threadIdx.x; i < n4;
         i += gridDim.x * blockDim.x) {
        float4 v = src[i];
        __nv_bfloat162 h01 = __floats2bfloat162_rn(v.x, v.y);
        __nv_bfloat162 h23 = __floats2bfloat162_rn(v.z, v.w);
        float2 f01 = __bfloat1622float2(h01);
        float2 f23 = __bfloat1622float2(h23);
        __nv_bfloat162 l01 = __floats2bfloat162_rn(v.x - f01.x, v.y - f01.y);
        __nv_bfloat162 l23 = __floats2bfloat162_rn(v.z - f23.x, v.w - f23.y);
        hi[i * 2 + 0] = h01;  hi[i * 2 + 1] = h23;
        lo[i * 2 + 0] = l01;  lo[i * 2 + 1] = l23;
    }
}

// ---------------------------------------------------------------------------
// Dense head
// ---------------------------------------------------------------------------
__global__ __launch_bounds__(256, 4)
void dense_kernel2(const float* __restrict__ dw,
                   const float* __restrict__ db,
                   float* __restrict__ out) {
    __shared__ float ws[8][H_ + 1];
    const int tid = threadIdx.x;
    const int h0 = blockIdx.x * 8;
#pragma unroll
    for (int i = 0; i < 32; i++) {
        int idx = tid + i * 256;
        int r = idx >> 10, c = idx & 1023;
        ws[r][c] = dw[(size_t)(h0 + r) * H_ + c];
    }
    __syncthreads();
    const int b = tid >> 3;
    const int hi = tid & 7;
    const float* p = g_pooled + b * H_;
    float acc = 0.f;
#pragma unroll 8
    for (int k = 0; k < H_; k++) acc += p[k] * ws[hi][k];
    const float pinv = 1.f / g_masksum[b];
    out[b * H_ + h0 + hi] = tanhf(acc * pinv + db[h0 + hi]);
}

// ---------------------------------------------------------------------------
// Row L2-normalize in place (rows of H_=1024)
// ---------------------------------------------------------------------------
__global__ void l2norm_kernel(float* __restrict__ data) {
    float4* row = reinterpret_cast<float4*>(data + (size_t)blockIdx.x * H_);
    float4 v = row[threadIdx.x];
    float ss = v.x * v.x + v.y * v.y + v.z * v.z + v.w * v.w;
#pragma unroll
    for (int o = 16; o > 0; o >>= 1)
        ss += __shfl_down_sync(0xffffffffu, ss, o);
    __shared__ float warp_s[8];
    if ((threadIdx.x & 31) == 0) warp_s[threadIdx.x >> 5] = ss;
    __syncthreads();
    if (threadIdx.x < 8) {
        float t = warp_s[threadIdx.x];
#pragma unroll
        for (int o = 4; o > 0; o >>= 1)
            t += __shfl_down_sync(0xffu, t, o);
        if (threadIdx.x == 0) warp_s[0] = t;
    }
    __syncthreads();
    float scale = 1.f / fmaxf(sqrtf(warp_s[0]), EPS);
    v.x *= scale; v.y *= scale; v.z *= scale; v.w *= scale;
    row[threadIdx.x] = v;
}

// ---------------------------------------------------------------------------
// MV GEMM via mma.sync bf16 (split hi/lo, 3 passes), 3-stage cp.async.
// CTA 128x128, BK=32, 4 warps (2x2), warp tile 64x64 -> 6:1 MMA:LDSM,
// 96KB smem, __launch_bounds__(128,2) -> 2 CTAs/SM.
// Tile rows are 64B (32 bf16); two rows packed per 128B line, swizzled:
//   chunk = (((r&1)<<2) | c16) ^ ((r>>1)&7), byte = (r>>1)*128 + chunk*16
// Stage (32768 B): Ahi @0, Alo @8192, Whi @16384, Wlo @24576.
// ---------------------------------------------------------------------------
#define NCH 32                  // 1024 / 32
#define STG 32768
#define NSTG 3
#define GT 128

__device__ __forceinline__ uint32_t sw32(int r, int c16) {
    uint32_t idx = (uint32_t)(((r & 1) << 2) | c16) ^ (uint32_t)((r >> 1) & 7);
    return (uint32_t)((r >> 1) * 128) + idx * 16;
}

__device__ __forceinline__ void stage_load(uint32_t smb, int s, int ch,
                                           int m0, int n0, int tid) {
    const int kt = ch * 32;
    const __nv_bfloat16* srcs[4] = {g_Ahi, g_Alo, g_Whi, g_Wlo};
    const int row0s[4] = {m0, m0, n0, n0};
#pragma unroll
    for (int t4 = 0; t4 < 4; t4++) {
        const __nv_bfloat16* src = srcs[t4];
        const int row0 = row0s[t4];
        const uint32_t tb = smb + s * STG + t4 * 8192;
#pragma unroll
        for (int it = 0; it < 4; it++) {
            int q = tid + it * GT;           // 0..511 chunks (128 rows x 4)
            int r = q >> 2, c16 = q & 3;
            const void* g = src + (size_t)(row0 + r) * H_ + kt + c16 * 8;
            CP16(tb + sw32(r, c16), g);
        }
    }
}

__global__ __launch_bounds__(GT, 2)
void mv_gemm_mma(const float* __restrict__ bias,
                 const float* __restrict__ mask,
                 float* __restrict__ C) {
    extern __shared__ char sm[];
    const uint32_t smb = smem_u32(sm);

    const int tid = threadIdx.x;
    const int wid = tid >> 5, lane = tid & 31;
    const int warp_m = wid & 1;        // 0..1 -> 64-row half
    const int warp_n = wid >> 1;       // 0..1 -> 64-col half
    const int m0 = blockIdx.y * 128, n0 = blockIdx.x * 128;

    float acc[4][8][4];
#pragma unroll
    for (int i = 0; i < 4; i++)
#pragma unroll
        for (int j = 0; j < 8; j++)
#pragma unroll
            for (int k = 0; k < 4; k++) acc[i][j][k] = 0.f;

    const int g8 = lane >> 3, i8 = lane & 7;
    const int a_r = warp_m * 64 + (g8 & 1) * 8 + i8;
    const int a_cadd = g8 >> 1;
    const int b_r = warp_n * 64 + (g8 >> 1) * 8 + i8;
    const int b_cadd = g8 & 1;

    stage_load(smb, 0, 0, m0, n0, tid);
    CP_COMMIT();
    stage_load(smb, 1, 1, m0, n0, tid);
    CP_COMMIT();

    int s = 0, sn = 2;
    for (int ch = 0; ch < NCH; ch++) {
        if (ch + 2 < NCH) {
            stage_load(smb, sn, ch + 2, m0, n0, tid);
            CP_COMMIT();
            CP_WAIT2();
        } else if (ch + 1 < NCH) {
            CP_WAIT1();
        } else {
            CP_WAIT0();
        }
        __syncthreads();

        const uint32_t ah = smb + s * STG;
        const uint32_t al = ah + 8192;
        const uint32_t wh = ah + 16384;
        const uint32_t wl = ah + 24576;

#pragma unroll
        for (int ks = 0; ks < 2; ks++) {
            uint32_t Ahi[4][4], Alo[4][4];
#pragma unroll
            for (int mt = 0; mt < 4; mt++) {
                int r = a_r + mt * 16;
                uint32_t off = sw32(r, ks * 2 + a_cadd);
                LDSM_X4(Ahi[mt][0], Ahi[mt][1], Ahi[mt][2], Ahi[mt][3], ah + off);
                LDSM_X4(Alo[mt][0], Alo[mt][1], Alo[mt][2], Alo[mt][3], al + off);
            }
            uint32_t Bhi[8][2], Blo[8][2];
#pragma unroll
            for (int bh = 0; bh < 4; bh++) {
                int r = b_r + bh * 16;
                uint32_t off = sw32(r, ks * 2 + b_cadd);
                uint32_t t0, t1, t2, t3;
                LDSM_X4(t0, t1, t2, t3, wh + off);
                Bhi[2 * bh][0] = t0; Bhi[2 * bh][1] = t1;
                Bhi[2 * bh + 1][0] = t2; Bhi[2 * bh + 1][1] = t3;
                LDSM_X4(t0, t1, t2, t3, wl + off);
                Blo[2 * bh][0] = t0; Blo[2 * bh][1] = t1;
                Blo[2 * bh + 1][0] = t2; Blo[2 * bh + 1][1] = t3;
            }
#pragma unroll
            for (int mt = 0; mt < 4; mt++)
#pragma unroll
                for (int ng = 0; ng < 8; ng++) {
                    MMA16816(acc[mt][ng], Ahi[mt], Bhi[ng]);
                    MMA16816(acc[mt][ng], Ahi[mt], Blo[ng]);
                    MMA16816(acc[mt][ng], Alo[mt], Bhi[ng]);
                }
        }
        __syncthreads();
        s = (s == NSTG - 1) ? 0 : s + 1;
        sn = (sn == NSTG - 1) ? 0 : sn + 1;
    }

    // epilogue: + bias, * mask, store float2 pairs
#pragma unroll
    for (int mt = 0; mt < 4; mt++) {
        const int r0 = m0 + warp_m * 64 + mt * 16 + (lane >> 2);
        const float mk0 = mask[r0];
        const float mk1 = mask[r0 + 8];
#pragma unroll
        for (int ng = 0; ng < 8; ng++) {
            const int c = n0 + warp_n * 64 + ng * 8 + 2 * (lane & 3);
            const float2 b2 = *reinterpret_cast<const float2*>(bias + c);
            float2 o0, o1;
            o0.x = (acc[mt][ng][0] + b2.x) * mk0;
            o0.y = (acc[mt][ng][1] + b2.y) * mk0;
            o1.x = (acc[mt][ng][2] + b2.x) * mk1;
            o1.y = (acc[mt][ng][3] + b2.y) * mk1;
            *reinterpret_cast<float2*>(C + (size_t)r0 * H_ + c) = o0;
            *reinterpret_cast<float2*>(C + (size_t)(r0 + 8) * H_ + c) = o1;
        }
    }
}

// ---------------------------------------------------------------------------
extern "C" void kernel_launch(void* const* d_in, const int* in_sizes, int n_in,
                              void* d_out, int out_size) {
    const float* hidden   = (const float*)d_in[0];
    const int*   ids      = (const int*)d_in[1];
    const float* attn     = (const float*)d_in[2];
    const float* dense_w  = (const float*)d_in[3];
    const float* dense_b  = (const float*)d_in[4];
    const float* sparse_w = (const float*)d_in[5];
    const float* sparse_b = (const float*)d_in[6];
    const float* mv_w     = (const float*)d_in[7];
    const float* mv_b     = (const float*)d_in[8];

    float* out        = (float*)d_out;
    float* out_dense  = out + OFF_DENSE;
    float* out_sparse = out + OFF_SPARSE;
    float* out_mv     = out + OFF_MV;

    __nv_bfloat16 *whi, *wlo;
    cudaGetSymbolAddress((void**)&whi, g_Whi);
    cudaGetSymbolAddress((void**)&wlo, g_Wlo);

    // 1. zero sparse region + accumulators
    zero_kernel<<<2048, 256>>>(out_sparse);

    // 2. mega pass: split hidden + pooled partials + sparse dots + masksum
    {
        dim3 g(B_, S_ / SCH);   // (32, 16)
        mega_pass<<<g, 256>>>(hidden, attn, sparse_w);
    }

    // 3. split W into bf16 hi/lo
    split_bf16_kernel<<<1024, 256>>>((const float4*)mv_w,
                                     (__nv_bfloat162*)whi,
                                     (__nv_bfloat162*)wlo, H_ * H_ / 4);

    // 4. MV GEMM (mma.sync, 4 warps x 64x64, 2 CTAs/SM)  (4th -> profiled)
    {
        const int smem_bytes = NSTG * STG;  // 98304
        cudaFuncSetAttribute(mv_gemm_mma,
                             cudaFuncAttributeMaxDynamicSharedMemorySize,
                             smem_bytes);
        dim3 g(H_ / 128, TOK / 128);        // (8, 128) = 1024 CTAs
        mv_gemm_mma<<<g, GT, smem_bytes>>>(mv_b, attn, out_mv);
    }

    // 5. MV per-token L2 norm
    l2norm_kernel<<<TOK, 256>>>(out_mv);

    // 6. sparse finalize
    sparse_finalize<<<TOK / 256, 256>>>(attn, sparse_b, ids, out_sparse);

    // 7. dense head + its L2 norm
    dense_kernel2<<<H_ / 8, 256>>>(dense_w, dense_b, out_dense);
    l2norm_kernel<<<B_, 256>>>(out_dense);
}